// round 15
// baseline (speedup 1.0000x reference)
#include <cuda_runtime.h>
#include <cuda_bf16.h>
#include <cstdint>

// Problem constants: B=64, D=2048, UNITS=1024, NW=64
#define Dd     2048
#define UNITSn 1024
#define NWn    64

// bf16 hi/lo planes: W [u][k] (4MB each), X [b][k] (256KB each).
__device__ __align__(16) __nv_bfloat16 g_Whi[UNITSn * Dd];
__device__ __align__(16) __nv_bfloat16 g_Wlo[UNITSn * Dd];
__device__ __align__(16) __nv_bfloat16 g_Xhi[64 * Dd];
__device__ __align__(16) __nv_bfloat16 g_Xlo[64 * Dd];

__device__ __forceinline__ unsigned mdiv(unsigned e, unsigned magic) {
    return (unsigned)(((unsigned long long)e * magic) >> 32);
}
__device__ __forceinline__ unsigned pack_bf16x2(float f0, float f1) {
    unsigned short a = __bfloat16_as_ushort(__float2bfloat16_rn(f0));
    unsigned short b = __bfloat16_as_ushort(__float2bfloat16_rn(f1));
    return (unsigned)a | ((unsigned)b << 16);
}
__device__ __forceinline__ float bf16_hi_f(float f) {
    return __bfloat162float(__float2bfloat16_rn(f));
}
__device__ __forceinline__ unsigned smem_u32(const void* p) {
    unsigned a;
    asm("{ .reg .u64 t; cvta.to.shared.u64 t, %1; cvt.u32.u64 %0, t; }"
        : "=r"(a) : "l"(p));
    return a;
}
__device__ __forceinline__ void cp16(unsigned s, const void* g) {
    asm volatile("cp.async.cg.shared.global [%0], [%1], 16;" :: "r"(s), "l"(g));
}
__device__ __forceinline__ void cp_commit() { asm volatile("cp.async.commit_group;"); }
__device__ __forceinline__ void cp_wait_all() {
    asm volatile("cp.async.wait_group 0;" ::: "memory");
}

// HMMA m16n8k16 bf16 -> fp32 accumulate (base sm_80+ feature, sm_103-safe).
__device__ __forceinline__ void mma_bf16(float* d, unsigned a0, unsigned a1,
                                         unsigned a2, unsigned a3,
                                         unsigned b0, unsigned b1) {
    asm volatile(
        "mma.sync.aligned.m16n8k16.row.col.f32.bf16.bf16.f32 "
        "{%0,%1,%2,%3}, {%4,%5,%6,%7}, {%8,%9}, {%0,%1,%2,%3};"
        : "+f"(d[0]), "+f"(d[1]), "+f"(d[2]), "+f"(d[3])
        : "r"(a0), "r"(a1), "r"(a2), "r"(a3), "r"(b0), "r"(b1));
}

// ---------------------------------------------------------------------------
// Kernel 1: build W bf16 hi/lo planes (2 units per CTA, 512 CTAs x 256 thr),
// convert x to bf16 hi/lo planes ONCE (threads 0-63: one float4 each), and
// seed out = bias. Scatter stores a single packed u32 (hi|lo<<16) per
// position; the dump splits planes with byte_perm, fully coalesced.
// ---------------------------------------------------------------------------
#define BTHR 256
#define KSTR 2080    // st row stride in u32
__global__ __launch_bounds__(BTHR) void build_w_kernel(const int* __restrict__ indices,
                                                       const float* __restrict__ w,
                                                       const float* __restrict__ x,
                                                       const float* __restrict__ bias,
                                                       float* __restrict__ out,
                                                       int L, unsigned magicL) {
    __shared__ unsigned st[2 * KSTR];     // [2 units][2048 k + pad] packed hi/lo
    __shared__ unsigned wpk[NWn];
    const int tid = threadIdx.x;
    const int u0  = blockIdx.x * 2;

    // Seed out = bias (512 blocks x 128 = 65536 = B*UNITS).
    if (tid < 128) {
        const int o = blockIdx.x * 128 + tid;
        out[o] = bias[o & (UNITSn - 1)];
    }
    // Convert x slice: 512 CTAs x 64 threads x float4 = 131072 floats.
    if (tid >= 128 && tid < 192) {
        const int o = (blockIdx.x * 64 + (tid - 128)) * 4;
        float4 f = __ldg((const float4*)(x + o));
        float h0 = bf16_hi_f(f.x), h1 = bf16_hi_f(f.y);
        float h2 = bf16_hi_f(f.z), h3 = bf16_hi_f(f.w);
        uint2 hv, lv;
        hv.x = pack_bf16x2(h0, h1); hv.y = pack_bf16x2(h2, h3);
        lv.x = pack_bf16x2(f.x - h0, f.y - h1);
        lv.y = pack_bf16x2(f.z - h2, f.w - h3);
        *(uint2*)&g_Xhi[o] = hv;
        *(uint2*)&g_Xlo[o] = lv;
    }
    // Precompute packed hi/lo bf16 of the 64 w values.
    if (tid < NWn) {
        const float wv = w[tid];
        const float h  = bf16_hi_f(wv);
        wpk[tid] = (unsigned)__bfloat16_as_ushort(__float2bfloat16_rn(h)) |
                   ((unsigned)__bfloat16_as_ushort(__float2bfloat16_rn(wv - h)) << 16);
    }
    // Zero st.
    #pragma unroll
    for (int i = 0; i < (2 * KSTR + 4 * BTHR - 1) / (4 * BTHR); i++) {
        const int idx = (i * BTHR + tid) * 4;
        if (idx + 3 < 2 * KSTR)
            *(uint4*)(st + idx) = make_uint4(0u, 0u, 0u, 0u);
    }
    for (int idx = (2 * KSTR / (4 * BTHR)) * 4 * BTHR + tid; idx < 2 * KSTR; idx += BTHR)
        st[idx] = 0u;
    __syncthreads();

    // Scatter: st[uu*KSTR + p] = wpk[bucket]. int4 index loads, paired.
    {
        const int NWL4 = 16 * L;
        const int4* ind4 = (const int4*)indices + (long)u0 * NWL4;
        int e4 = tid;
        for (; e4 + BTHR < NWL4; e4 += 2 * BTHR) {
            int4 v[2], v2[2];
            #pragma unroll
            for (int uu = 0; uu < 2; uu++) {
                v[uu]  = __ldg(ind4 + (long)uu * NWL4 + e4);
                v2[uu] = __ldg(ind4 + (long)uu * NWL4 + e4 + BTHR);
            }
            #pragma unroll
            for (int h = 0; h < 2; h++) {
                const int4* vv = h ? v2 : v;
                const int e = (e4 + h * BTHR) * 4;
                const unsigned k0 = mdiv(e, magicL),     k1 = mdiv(e + 1, magicL);
                const unsigned k2 = mdiv(e + 2, magicL), k3 = mdiv(e + 3, magicL);
                #pragma unroll
                for (int uu = 0; uu < 2; uu++) {
                    unsigned* row = st + uu * KSTR;
                    unsigned p;
                    p = (unsigned)(vv[uu].x - 1); if (p < (unsigned)Dd) row[p] = wpk[k0];
                    p = (unsigned)(vv[uu].y - 1); if (p < (unsigned)Dd) row[p] = wpk[k1];
                    p = (unsigned)(vv[uu].z - 1); if (p < (unsigned)Dd) row[p] = wpk[k2];
                    p = (unsigned)(vv[uu].w - 1); if (p < (unsigned)Dd) row[p] = wpk[k3];
                }
            }
        }
        for (; e4 < NWL4; e4 += BTHR) {
            int4 v[2];
            #pragma unroll
            for (int uu = 0; uu < 2; uu++)
                v[uu] = __ldg(ind4 + (long)uu * NWL4 + e4);
            const int e = e4 * 4;
            const unsigned k0 = mdiv(e, magicL),     k1 = mdiv(e + 1, magicL);
            const unsigned k2 = mdiv(e + 2, magicL), k3 = mdiv(e + 3, magicL);
            #pragma unroll
            for (int uu = 0; uu < 2; uu++) {
                unsigned* row = st + uu * KSTR;
                unsigned p;
                p = (unsigned)(v[uu].x - 1); if (p < (unsigned)Dd) row[p] = wpk[k0];
                p = (unsigned)(v[uu].y - 1); if (p < (unsigned)Dd) row[p] = wpk[k1];
                p = (unsigned)(v[uu].z - 1); if (p < (unsigned)Dd) row[p] = wpk[k2];
                p = (unsigned)(v[uu].w - 1); if (p < (unsigned)Dd) row[p] = wpk[k3];
            }
        }
    }
    __syncthreads();

    // Dump: uint4 = 4 packed k -> uint2 per plane via byte_perm; coalesced.
    #pragma unroll
    for (int uu = 0; uu < 2; uu++) {
        #pragma unroll
        for (int i = 0; i < 2; i++) {
            const int idx = i * BTHR + tid;             // 0..511 uint4 groups
            uint4 pk = *(const uint4*)(st + uu * KSTR + idx * 4);
            uint2 hv, lv;
            hv.x = __byte_perm(pk.x, pk.y, 0x5410);
            hv.y = __byte_perm(pk.z, pk.w, 0x5410);
            lv.x = __byte_perm(pk.x, pk.y, 0x7632);
            lv.y = __byte_perm(pk.z, pk.w, 0x7632);
            const long gi = (long)(u0 + uu) * Dd + idx * 4;
            *(uint2*)&g_Whi[gi] = hv;
            *(uint2*)&g_Wlo[gi] = lv;
        }
    }
}

// ---------------------------------------------------------------------------
// Kernel 2: HMMA GEMM, pure cp.async prologue (NO conversion — all four
// operand planes are prebuilt bf16). Grid (16 ug, 8 ks), 256 threads.
// Per CTA: units [ug*64, +64), k [ks*256, +256); 128KB smem, padded rows.
// Warp w: batch tile m0=(w&3)*16, unit tile n0=(w>>2)*32; 3 error-compensated
// passes x 16 k-steps x 4 n-subtiles; atomicAdd into bias-seeded out.
// ---------------------------------------------------------------------------
#define ROWW  132
#define WS_HI 0
#define WS_LO (64 * ROWW)
#define XS_HI (128 * ROWW)
#define XS_LO (192 * ROWW)
#define SM_WORDS (256 * ROWW)          // 135168 B

__global__ __launch_bounds__(256, 1) void gemm_kernel(float* __restrict__ out) {
    extern __shared__ unsigned smw[];
    const unsigned sbase = smem_u32(smw);
    const int tid  = threadIdx.x;
    const int lane = tid & 31;
    const int warp = tid >> 5;
    const int u0   = blockIdx.x * 64;
    const int k0   = blockIdx.y * 256;

    // Prologue: 32 cp.async per thread (W hi/lo 64KB + X hi/lo 64KB).
    #pragma unroll
    for (int i = 0; i < 8; i++) {
        const int idx = i * 256 + tid;       // 0..2047 16B-chunks
        const int r   = idx >> 5;            // row (unit or batch)
        const int c   = idx & 31;            // 16B chunk within 512B row
        const unsigned soff = (r * ROWW + c * 4) * 4;
        const long wsrc = (long)(u0 + r) * Dd + k0 + c * 8;
        const long xsrc = (long)r * Dd + k0 + c * 8;
        cp16(sbase + WS_HI * 4 + soff, &g_Whi[wsrc]);
        cp16(sbase + WS_LO * 4 + soff, &g_Wlo[wsrc]);
        cp16(sbase + XS_HI * 4 + soff, &g_Xhi[xsrc]);
        cp16(sbase + XS_LO * 4 + soff, &g_Xlo[xsrc]);
    }
    cp_commit();
    cp_wait_all();
    __syncthreads();

    // Fragments: g = lane>>2 (row/col group), tig = lane&3 (k sub-pair).
    const int g   = lane >> 2;
    const int tig = lane & 3;
    const int m0  = (warp & 3) * 16;
    const int n0  = (warp >> 2) * 32;

    const unsigned* ah0 = smw + XS_HI + (m0 + g) * ROWW + tig;
    const unsigned* ah8 = ah0 + 8 * ROWW;
    const unsigned* al0 = ah0 + (XS_LO - XS_HI);
    const unsigned* al8 = ah8 + (XS_LO - XS_HI);

    float d[4][4];
    #pragma unroll
    for (int j = 0; j < 4; j++)
        #pragma unroll
        for (int i = 0; i < 4; i++) d[j][i] = 0.f;

    #pragma unroll 4
    for (int s = 0; s < 16; s++) {
        const int co = s * 8;
        const unsigned xh0 = ah0[co], xh1 = ah8[co], xh2 = ah0[co + 4], xh3 = ah8[co + 4];
        const unsigned xl0 = al0[co], xl1 = al8[co], xl2 = al0[co + 4], xl3 = al8[co + 4];
        #pragma unroll
        for (int j = 0; j < 4; j++) {
            const unsigned* wb = smw + WS_HI + (n0 + j * 8 + g) * ROWW + tig;
            const unsigned bh0 = wb[co], bh1 = wb[co + 4];
            const unsigned bl0 = wb[WS_LO + co], bl1 = wb[WS_LO + co + 4];
            mma_bf16(d[j], xh0, xh1, xh2, xh3, bh0, bh1);   // hi*hi
            mma_bf16(d[j], xl0, xl1, xl2, xl3, bh0, bh1);   // lo*hi
            mma_bf16(d[j], xh0, xh1, xh2, xh3, bl0, bl1);   // hi*lo
        }
    }

    // Epilogue: atomic k-split reduction into bias-seeded out.
    #pragma unroll
    for (int j = 0; j < 4; j++) {
        const int u = u0 + n0 + j * 8 + 2 * tig;
        float* p0 = out + (long)(m0 + g) * UNITSn + u;
        float* p1 = out + (long)(m0 + g + 8) * UNITSn + u;
        atomicAdd(p0,     d[j][0]);
        atomicAdd(p0 + 1, d[j][1]);
        atomicAdd(p1,     d[j][2]);
        atomicAdd(p1 + 1, d[j][3]);
    }
}

// ---------------------------------------------------------------------------
extern "C" void kernel_launch(void* const* d_in, const int* in_sizes, int n_in,
                              void* d_out, int out_size) {
    const float* x       = (const float*)d_in[0];
    const float* w       = (const float*)d_in[1];
    const float* bias    = (const float*)d_in[2];
    const int*   indices = (const int*)d_in[3];
    float*       out     = (float*)d_out;

    const int L = in_sizes[3] / (UNITSn * NWn);
    const unsigned magicL =
        (unsigned)((0x100000000ULL + (unsigned long long)L - 1) / (unsigned long long)L);

    const int gemm_smem = SM_WORDS * (int)sizeof(unsigned);   // 135,168 B
    cudaFuncSetAttribute(gemm_kernel, cudaFuncAttributeMaxDynamicSharedMemorySize,
                         gemm_smem);

    build_w_kernel<<<512, BTHR>>>(indices, w, x, bias, out, L, magicL);
    gemm_kernel<<<dim3(16, 8), 256, gemm_smem>>>(out);
}

// round 16
// speedup vs baseline: 1.0583x; 1.0583x over previous
#include <cuda_runtime.h>
#include <cuda_bf16.h>
#include <cstdint>

// Problem constants: B=64, D=2048, UNITS=1024, NW=64
#define Dd     2048
#define UNITSn 1024
#define NWn    64

// bf16 hi/lo planes: W [u][k] (4MB each), X [b][k] (256KB each).
__device__ __align__(16) __nv_bfloat16 g_Whi[UNITSn * Dd];
__device__ __align__(16) __nv_bfloat16 g_Wlo[UNITSn * Dd];
__device__ __align__(16) __nv_bfloat16 g_Xhi[64 * Dd];
__device__ __align__(16) __nv_bfloat16 g_Xlo[64 * Dd];

__device__ __forceinline__ unsigned mdiv(unsigned e, unsigned magic) {
    return (unsigned)(((unsigned long long)e * magic) >> 32);
}
__device__ __forceinline__ unsigned pack_bf16x2(float f0, float f1) {
    unsigned short a = __bfloat16_as_ushort(__float2bfloat16_rn(f0));
    unsigned short b = __bfloat16_as_ushort(__float2bfloat16_rn(f1));
    return (unsigned)a | ((unsigned)b << 16);
}
__device__ __forceinline__ float bf16_hi_f(float f) {
    return __bfloat162float(__float2bfloat16_rn(f));
}
__device__ __forceinline__ unsigned smem_u32(const void* p) {
    unsigned a;
    asm("{ .reg .u64 t; cvta.to.shared.u64 t, %1; cvt.u32.u64 %0, t; }"
        : "=r"(a) : "l"(p));
    return a;
}
__device__ __forceinline__ void cp16(unsigned s, const void* g) {
    asm volatile("cp.async.cg.shared.global [%0], [%1], 16;" :: "r"(s), "l"(g));
}
__device__ __forceinline__ void cp_commit() { asm volatile("cp.async.commit_group;"); }
__device__ __forceinline__ void cp_wait_all() {
    asm volatile("cp.async.wait_group 0;" ::: "memory");
}

// HMMA m16n8k16 bf16 -> fp32 accumulate (base sm_80+ feature, sm_103-safe).
__device__ __forceinline__ void mma_bf16(float* d, unsigned a0, unsigned a1,
                                         unsigned a2, unsigned a3,
                                         unsigned b0, unsigned b1) {
    asm volatile(
        "mma.sync.aligned.m16n8k16.row.col.f32.bf16.bf16.f32 "
        "{%0,%1,%2,%3}, {%4,%5,%6,%7}, {%8,%9}, {%0,%1,%2,%3};"
        : "+f"(d[0]), "+f"(d[1]), "+f"(d[2]), "+f"(d[3])
        : "r"(a0), "r"(a1), "r"(a2), "r"(a3), "r"(b0), "r"(b1));
}

// ---------------------------------------------------------------------------
// Kernel 1: build W bf16 hi/lo planes (2 units per CTA, 512 CTAs x 256 thr),
// convert x to bf16 hi/lo planes ONCE, and seed out = bias. Scatter stores a
// single packed u32 (hi|lo<<16) per position; dump splits planes (byte_perm).
// ---------------------------------------------------------------------------
#define BTHR 256
#define KSTR 2080    // st row stride in u32
__global__ __launch_bounds__(BTHR) void build_w_kernel(const int* __restrict__ indices,
                                                       const float* __restrict__ w,
                                                       const float* __restrict__ x,
                                                       const float* __restrict__ bias,
                                                       float* __restrict__ out,
                                                       int L, unsigned magicL) {
    __shared__ unsigned st[2 * KSTR];     // [2 units][2048 k + pad] packed hi/lo
    __shared__ unsigned wpk[NWn];
    const int tid = threadIdx.x;
    const int u0  = blockIdx.x * 2;

    // Seed out = bias (512 blocks x 128 = 65536 = B*UNITS).
    if (tid < 128) {
        const int o = blockIdx.x * 128 + tid;
        out[o] = bias[o & (UNITSn - 1)];
    }
    // Convert x slice: 512 CTAs x 64 threads x float4 = 131072 floats.
    if (tid >= 128 && tid < 192) {
        const int o = (blockIdx.x * 64 + (tid - 128)) * 4;
        float4 f = __ldg((const float4*)(x + o));
        float h0 = bf16_hi_f(f.x), h1 = bf16_hi_f(f.y);
        float h2 = bf16_hi_f(f.z), h3 = bf16_hi_f(f.w);
        uint2 hv, lv;
        hv.x = pack_bf16x2(h0, h1); hv.y = pack_bf16x2(h2, h3);
        lv.x = pack_bf16x2(f.x - h0, f.y - h1);
        lv.y = pack_bf16x2(f.z - h2, f.w - h3);
        *(uint2*)&g_Xhi[o] = hv;
        *(uint2*)&g_Xlo[o] = lv;
    }
    // Precompute packed hi/lo bf16 of the 64 w values.
    if (tid < NWn) {
        const float wv = w[tid];
        const float h  = bf16_hi_f(wv);
        wpk[tid] = (unsigned)__bfloat16_as_ushort(__float2bfloat16_rn(h)) |
                   ((unsigned)__bfloat16_as_ushort(__float2bfloat16_rn(wv - h)) << 16);
    }
    // Zero st.
    #pragma unroll
    for (int i = 0; i < (2 * KSTR + 4 * BTHR - 1) / (4 * BTHR); i++) {
        const int idx = (i * BTHR + tid) * 4;
        if (idx + 3 < 2 * KSTR)
            *(uint4*)(st + idx) = make_uint4(0u, 0u, 0u, 0u);
    }
    for (int idx = (2 * KSTR / (4 * BTHR)) * 4 * BTHR + tid; idx < 2 * KSTR; idx += BTHR)
        st[idx] = 0u;
    __syncthreads();

    // Scatter: st[uu*KSTR + p] = wpk[bucket]. int4 index loads, paired.
    {
        const int NWL4 = 16 * L;
        const int4* ind4 = (const int4*)indices + (long)u0 * NWL4;
        int e4 = tid;
        for (; e4 + BTHR < NWL4; e4 += 2 * BTHR) {
            int4 v[2], v2[2];
            #pragma unroll
            for (int uu = 0; uu < 2; uu++) {
                v[uu]  = __ldg(ind4 + (long)uu * NWL4 + e4);
                v2[uu] = __ldg(ind4 + (long)uu * NWL4 + e4 + BTHR);
            }
            #pragma unroll
            for (int h = 0; h < 2; h++) {
                const int4* vv = h ? v2 : v;
                const int e = (e4 + h * BTHR) * 4;
                const unsigned k0 = mdiv(e, magicL),     k1 = mdiv(e + 1, magicL);
                const unsigned k2 = mdiv(e + 2, magicL), k3 = mdiv(e + 3, magicL);
                #pragma unroll
                for (int uu = 0; uu < 2; uu++) {
                    unsigned* row = st + uu * KSTR;
                    unsigned p;
                    p = (unsigned)(vv[uu].x - 1); if (p < (unsigned)Dd) row[p] = wpk[k0];
                    p = (unsigned)(vv[uu].y - 1); if (p < (unsigned)Dd) row[p] = wpk[k1];
                    p = (unsigned)(vv[uu].z - 1); if (p < (unsigned)Dd) row[p] = wpk[k2];
                    p = (unsigned)(vv[uu].w - 1); if (p < (unsigned)Dd) row[p] = wpk[k3];
                }
            }
        }
        for (; e4 < NWL4; e4 += BTHR) {
            int4 v[2];
            #pragma unroll
            for (int uu = 0; uu < 2; uu++)
                v[uu] = __ldg(ind4 + (long)uu * NWL4 + e4);
            const int e = e4 * 4;
            const unsigned k0 = mdiv(e, magicL),     k1 = mdiv(e + 1, magicL);
            const unsigned k2 = mdiv(e + 2, magicL), k3 = mdiv(e + 3, magicL);
            #pragma unroll
            for (int uu = 0; uu < 2; uu++) {
                unsigned* row = st + uu * KSTR;
                unsigned p;
                p = (unsigned)(v[uu].x - 1); if (p < (unsigned)Dd) row[p] = wpk[k0];
                p = (unsigned)(v[uu].y - 1); if (p < (unsigned)Dd) row[p] = wpk[k1];
                p = (unsigned)(v[uu].z - 1); if (p < (unsigned)Dd) row[p] = wpk[k2];
                p = (unsigned)(v[uu].w - 1); if (p < (unsigned)Dd) row[p] = wpk[k3];
            }
        }
    }
    __syncthreads();

    // Dump: uint4 = 4 packed k -> uint2 per plane via byte_perm; coalesced.
    #pragma unroll
    for (int uu = 0; uu < 2; uu++) {
        #pragma unroll
        for (int i = 0; i < 2; i++) {
            const int idx = i * BTHR + tid;             // 0..511 uint4 groups
            uint4 pk = *(const uint4*)(st + uu * KSTR + idx * 4);
            uint2 hv, lv;
            hv.x = __byte_perm(pk.x, pk.y, 0x5410);
            hv.y = __byte_perm(pk.z, pk.w, 0x5410);
            lv.x = __byte_perm(pk.x, pk.y, 0x7632);
            lv.y = __byte_perm(pk.z, pk.w, 0x7632);
            const long gi = (long)(u0 + uu) * Dd + idx * 4;
            *(uint2*)&g_Whi[gi] = hv;
            *(uint2*)&g_Wlo[gi] = lv;
        }
    }
}

// ---------------------------------------------------------------------------
// Kernel 2: HMMA GEMM, pure cp.async prologue. Grid (16 ug, 8 ks), 256 thr.
// KEY CHANGE vs R15: each error-compensation pass accumulates into its OWN
// register set (dhh / dlh / dhl, merged in the epilogue). This turns 4
// 48-deep serial HMMA chains per warp into 12 independent 16-deep chains,
// unblocking the tensor pipe's latency.
// ---------------------------------------------------------------------------
#define ROWW  132
#define WS_HI 0
#define WS_LO (64 * ROWW)
#define XS_HI (128 * ROWW)
#define XS_LO (192 * ROWW)
#define SM_WORDS (256 * ROWW)          // 135168 B

__global__ __launch_bounds__(256, 1) void gemm_kernel(float* __restrict__ out) {
    extern __shared__ unsigned smw[];
    const unsigned sbase = smem_u32(smw);
    const int tid  = threadIdx.x;
    const int lane = tid & 31;
    const int warp = tid >> 5;
    const int u0   = blockIdx.x * 64;
    const int k0   = blockIdx.y * 256;

    // Prologue: 32 cp.async per thread (W hi/lo 64KB + X hi/lo 64KB).
    #pragma unroll
    for (int i = 0; i < 8; i++) {
        const int idx = i * 256 + tid;       // 0..2047 16B-chunks
        const int r   = idx >> 5;
        const int c   = idx & 31;
        const unsigned soff = (r * ROWW + c * 4) * 4;
        const long wsrc = (long)(u0 + r) * Dd + k0 + c * 8;
        const long xsrc = (long)r * Dd + k0 + c * 8;
        cp16(sbase + WS_HI * 4 + soff, &g_Whi[wsrc]);
        cp16(sbase + WS_LO * 4 + soff, &g_Wlo[wsrc]);
        cp16(sbase + XS_HI * 4 + soff, &g_Xhi[xsrc]);
        cp16(sbase + XS_LO * 4 + soff, &g_Xlo[xsrc]);
    }
    cp_commit();
    cp_wait_all();
    __syncthreads();

    // Fragments: g = lane>>2 (row/col group), tig = lane&3 (k sub-pair).
    const int g   = lane >> 2;
    const int tig = lane & 3;
    const int m0  = (warp & 3) * 16;
    const int n0  = (warp >> 2) * 32;

    const unsigned* ah0 = smw + XS_HI + (m0 + g) * ROWW + tig;
    const unsigned* ah8 = ah0 + 8 * ROWW;
    const unsigned* al0 = ah0 + (XS_LO - XS_HI);
    const unsigned* al8 = ah8 + (XS_LO - XS_HI);

    float dhh[4][4], dlh[4][4], dhl[4][4];
    #pragma unroll
    for (int j = 0; j < 4; j++)
        #pragma unroll
        for (int i = 0; i < 4; i++) { dhh[j][i] = 0.f; dlh[j][i] = 0.f; dhl[j][i] = 0.f; }

    #pragma unroll 4
    for (int s = 0; s < 16; s++) {
        const int co = s * 8;
        const unsigned xh0 = ah0[co], xh1 = ah8[co], xh2 = ah0[co + 4], xh3 = ah8[co + 4];
        const unsigned xl0 = al0[co], xl1 = al8[co], xl2 = al0[co + 4], xl3 = al8[co + 4];
        #pragma unroll
        for (int j = 0; j < 4; j++) {
            const unsigned* wb = smw + WS_HI + (n0 + j * 8 + g) * ROWW + tig;
            const unsigned bh0 = wb[co], bh1 = wb[co + 4];
            const unsigned bl0 = wb[WS_LO + co], bl1 = wb[WS_LO + co + 4];
            mma_bf16(dhh[j], xh0, xh1, xh2, xh3, bh0, bh1);   // hi*hi
            mma_bf16(dlh[j], xl0, xl1, xl2, xl3, bh0, bh1);   // lo*hi
            mma_bf16(dhl[j], xh0, xh1, xh2, xh3, bl0, bl1);   // hi*lo
        }
    }

    // Epilogue: merge the three passes, atomic k-split reduction into out.
    #pragma unroll
    for (int j = 0; j < 4; j++) {
        const int u = u0 + n0 + j * 8 + 2 * tig;
        float* p0 = out + (long)(m0 + g) * UNITSn + u;
        float* p1 = out + (long)(m0 + g + 8) * UNITSn + u;
        atomicAdd(p0,     dhh[j][0] + dlh[j][0] + dhl[j][0]);
        atomicAdd(p0 + 1, dhh[j][1] + dlh[j][1] + dhl[j][1]);
        atomicAdd(p1,     dhh[j][2] + dlh[j][2] + dhl[j][2]);
        atomicAdd(p1 + 1, dhh[j][3] + dlh[j][3] + dhl[j][3]);
    }
}

// ---------------------------------------------------------------------------
extern "C" void kernel_launch(void* const* d_in, const int* in_sizes, int n_in,
                              void* d_out, int out_size) {
    const float* x       = (const float*)d_in[0];
    const float* w       = (const float*)d_in[1];
    const float* bias    = (const float*)d_in[2];
    const int*   indices = (const int*)d_in[3];
    float*       out     = (float*)d_out;

    const int L = in_sizes[3] / (UNITSn * NWn);
    const unsigned magicL =
        (unsigned)((0x100000000ULL + (unsigned long long)L - 1) / (unsigned long long)L);

    const int gemm_smem = SM_WORDS * (int)sizeof(unsigned);   // 135,168 B
    cudaFuncSetAttribute(gemm_kernel, cudaFuncAttributeMaxDynamicSharedMemorySize,
                         gemm_smem);

    build_w_kernel<<<512, BTHR>>>(indices, w, x, bias, out, L, magicL);
    gemm_kernel<<<dim3(16, 8), 256, gemm_smem>>>(out);
}